// round 16
// baseline (speedup 1.0000x reference)
#include <cuda_runtime.h>
#include <cstddef>

// ============================================================================
// CommNetActor — algebraically collapsed + f32x2 FMA + MUFU-free sigmoid.
//
//   H0 = sigmoid(O @ W_enc + b_enc);  out[b] = H0[b].flatten() @ M + const
//
// R13 post-mortem: decoder read gMT with 32-line LDG.128s (L1tex wavefront
// storm, ~220us) and 8 warps couldn't hide latency (issue 23.6%).
// R14: (a) decoder stages row-major gM via smem tiles (coalesced LDG, 1-wf
// LDS rows), H stored quad-interleaved sHT[r][b0..b3] so one broadcast
// LDS.128 = two packed f32x2 operands; (b) TPB 512 (16 warps), encoder tile
// 4x4 with the same conflict-free W mapping.
// ============================================================================

#define TPB 512
#define BPC 4
#define NBATCH 8192

typedef unsigned long long u64;

__device__ float gE[64 * 64];
__device__ float gT[64 * 32];
__device__ float gConst[32];
__device__ float gWsum[64 * 32];
__device__ float gM[4096 * 32];      // row-major: [a*64+k][n]

// ---------------------------------------------------------------------------
__device__ __forceinline__ void ffma2(u64& d, u64 a, u64 b) {
    asm("fma.rn.f32x2 %0, %1, %2, %0;" : "+l"(d) : "l"(a), "l"(b));
}
__device__ __forceinline__ u64 add2(u64 a, u64 b) {
    u64 d; asm("add.rn.f32x2 %0, %1, %2;" : "=l"(d) : "l"(a), "l"(b)); return d;
}
__device__ __forceinline__ float unpack_sum(u64 v) {
    float lo, hi;
    asm("mov.b64 {%0, %1}, %2;" : "=f"(lo), "=f"(hi) : "l"(v));
    return lo + hi;
}
__device__ __forceinline__ void unpack2(u64 v, float& lo, float& hi) {
    asm("mov.b64 {%0, %1}, %2;" : "=f"(lo), "=f"(hi) : "l"(v));
}
__device__ __forceinline__ u64 dup2(float m) {
    u64 d; asm("mov.b64 %0, {%1, %1};" : "=l"(d) : "f"(m)); return d;
}

// MUFU-free sigmoid: 1/(1+2^(-x*log2e)). ~18 FMA/ALU ops, rel err ~3e-6.
__device__ __forceinline__ float fast_sigmoid(float x) {
    float t = x * -1.44269504088896f;
    t = fminf(fmaxf(t, -126.0f), 126.0f);
    float fi = t + 12582912.0f;
    int   ib = __float_as_int(fi) - 0x4B400000;
    float f  = t - (fi - 12582912.0f);
    float p  = 1.3333558e-3f;
    p = fmaf(p, f, 9.6181291e-3f);
    p = fmaf(p, f, 5.5504109e-2f);
    p = fmaf(p, f, 2.4022651e-1f);
    p = fmaf(p, f, 6.9314718e-1f);
    p = fmaf(p, f, 1.0f);
    float e = __int_as_float(__float_as_int(p) + (int)((unsigned)ib << 23));
    float d = 1.0f + e;
    float r = __int_as_float(0x7EF311C3 - __float_as_int(d));
    r = r * (2.0f - d * r);
    r = r * (2.0f - d * r);
    return r;
}

// ---------------------------------------------------------------------------
// P0: Wsum[d][n] = sum_a Wdec[(a*64+d)][n].
// ---------------------------------------------------------------------------
__global__ void p0_wsum(const float* __restrict__ Wdec)
{
    int idx = blockIdx.x * 256 + threadIdx.x;
    float s = 0.0f;
#pragma unroll 8
    for (int a = 0; a < 64; a++) s += Wdec[a * 2048 + idx];
    gWsum[idx] = s;
}

// ---------------------------------------------------------------------------
// P1: compose 4 comm layers -> E, F, g; then T = (1/64) F Wsum, const.
// ---------------------------------------------------------------------------
#define P1_TPB 512
#define P1_WSTRIDE 68

__global__ void p1_compose(const float* __restrict__ W1, const float* __restrict__ b1,
                           const float* __restrict__ W2, const float* __restrict__ b2,
                           const float* __restrict__ W3, const float* __restrict__ b3,
                           const float* __restrict__ W4, const float* __restrict__ b4,
                           const float* __restrict__ bdec)
{
    extern __shared__ float sm[];
    float* sE   = sm;                      // 4096
    float* sF   = sm + 4096;               // 4096
    float* sWeT = sm + 8192;               // 4352
    float* sWbT = sm + 12544;              // 4352
    float* sG   = sm + 16896;              // 64

    const int t = threadIdx.x;

#pragma unroll
    for (int c = 0; c < 8; c++) {
        int idx = t + P1_TPB * c;
        sE[idx] = ((idx >> 6) == (idx & 63)) ? 1.0f : 0.0f;
        sF[idx] = 0.0f;
    }
    if (t < 64) sG[t] = 0.0f;

    const float* Ws[4] = {W1, W2, W3, W4};
    const float* bs[4] = {b1, b2, b3, b4};

    const int ti = t >> 5;
    const int tj = t & 31;
    const int i0 = ti * 4;

#pragma unroll 1
    for (int l = 0; l < 4; l++) {
        const float* W = Ws[l];
#pragma unroll
        for (int c = 0; c < 8; c++) {
            int idx = t + P1_TPB * c;
            int k = idx >> 6, j = idx & 63;
            float wt = W[idx];
            float wb = W[4096 + idx];
            sWeT[j * P1_WSTRIDE + k] = wt - wb * (1.0f / 64.0f);
            sWbT[j * P1_WSTRIDE + k] = wb;
        }
        __syncthreads();

        u64 aE[4][2], aF[4][2];
#pragma unroll
        for (int r = 0; r < 4; r++) {
            aE[r][0] = 0; aE[r][1] = 0; aF[r][0] = 0; aF[r][1] = 0;
        }

#pragma unroll 2
        for (int kk = 0; kk < 64; kk += 4) {
            ulonglong2 we0 = *(const ulonglong2*)&sWeT[tj * P1_WSTRIDE + kk];
            ulonglong2 we1 = *(const ulonglong2*)&sWeT[(tj + 32) * P1_WSTRIDE + kk];
            ulonglong2 wb0 = *(const ulonglong2*)&sWbT[tj * P1_WSTRIDE + kk];
            ulonglong2 wb1 = *(const ulonglong2*)&sWbT[(tj + 32) * P1_WSTRIDE + kk];
            u64 ws0x = add2(we0.x, wb0.x), ws0y = add2(we0.y, wb0.y);
            u64 ws1x = add2(we1.x, wb1.x), ws1y = add2(we1.y, wb1.y);
#pragma unroll
            for (int r = 0; r < 4; r++) {
                ulonglong2 e2 = *(const ulonglong2*)&sE[(i0 + r) * 64 + kk];
                ulonglong2 f2 = *(const ulonglong2*)&sF[(i0 + r) * 64 + kk];
                ffma2(aE[r][0], e2.x, we0.x); ffma2(aE[r][0], e2.y, we0.y);
                ffma2(aE[r][1], e2.x, we1.x); ffma2(aE[r][1], e2.y, we1.y);
                ffma2(aF[r][0], f2.x, ws0x); ffma2(aF[r][0], f2.y, ws0y);
                ffma2(aF[r][0], e2.x, wb0.x); ffma2(aF[r][0], e2.y, wb0.y);
                ffma2(aF[r][1], f2.x, ws1x); ffma2(aF[r][1], f2.y, ws1y);
                ffma2(aF[r][1], e2.x, wb1.x); ffma2(aF[r][1], e2.y, wb1.y);
            }
        }

        float gnew = 0.0f;
        if (t < 64) {
            for (int k = 0; k < 64; k++)
                gnew += sG[k] * (sWeT[t * P1_WSTRIDE + k] + sWbT[t * P1_WSTRIDE + k]);
            gnew += bs[l][t];
        }
        __syncthreads();

#pragma unroll
        for (int r = 0; r < 4; r++) {
            sE[(i0 + r) * 64 + tj]      = unpack_sum(aE[r][0]);
            sE[(i0 + r) * 64 + tj + 32] = unpack_sum(aE[r][1]);
            sF[(i0 + r) * 64 + tj]      = unpack_sum(aF[r][0]);
            sF[(i0 + r) * 64 + tj + 32] = unpack_sum(aF[r][1]);
        }
        if (t < 64) sG[t] = gnew;
    }
    __syncthreads();

    float* sWsum = sWeT;
#pragma unroll
    for (int c = 0; c < 4; c++) {
        int idx = t + P1_TPB * c;
        sWsum[idx] = gWsum[idx];
    }
    __syncthreads();

#pragma unroll
    for (int c = 0; c < 4; c++) {
        int idx = t + P1_TPB * c;
        int k = idx >> 5, n = idx & 31;
        float s = 0.0f;
#pragma unroll 8
        for (int d = 0; d < 64; d++) s += sF[k * 64 + d] * sWsum[d * 32 + n];
        gT[idx] = s * (1.0f / 64.0f);
    }
    if (t < 32) {
        float s = 0.0f;
        for (int d = 0; d < 64; d++) s += sG[d] * sWsum[d * 32 + t];
        gConst[t] = s + bdec[t];
    }
#pragma unroll
    for (int c = 0; c < 8; c++) { int idx = t + P1_TPB * c; gE[idx] = sE[idx]; }
}

// ---------------------------------------------------------------------------
// P2: gM[a*64+k][n] = sum_d E[k][d] * Wdec[(a*64+d)][n] + T[k][n]  (row-major)
// ---------------------------------------------------------------------------
__global__ void p2_buildM(const float* __restrict__ Wdec)
{
    __shared__ float sWd[2048];        // Wdec_a  [64][32]
    __shared__ float sE2[64 * 65];     // E padded
    const int a = blockIdx.x;
    const int t = threadIdx.x;

#pragma unroll
    for (int c = 0; c < 8; c++)  sWd[t + 256 * c] = Wdec[a * 2048 + t + 256 * c];
#pragma unroll
    for (int c = 0; c < 16; c++) {
        int i = t + 256 * c;
        sE2[(i >> 6) * 65 + (i & 63)] = gE[i];
    }
    __syncthreads();

#pragma unroll
    for (int c = 0; c < 8; c++) {
        int idx = t + 256 * c;
        int k = idx >> 5, n = idx & 31;
        float acc = gT[idx];
#pragma unroll 8
        for (int d = 0; d < 64; d++)
            acc += sE2[k * 65 + d] * sWd[d * 32 + n];
        gM[a * 2048 + idx] = acc;
    }
}

// ---------------------------------------------------------------------------
// Main fused kernel, 512 threads. Encoder tile 4 rows x 4 cols
// (cols {cg,cg+16,cg+32,cg+48}); H stored quad-interleaved sHT[r][b0..b3];
// decoder stages gM in 8 x 64KB smem tiles (aliasing dead sWT/sO).
// ---------------------------------------------------------------------------
#define WT_STRIDE 132

__global__ __launch_bounds__(TPB, 1)
void main_kernel(const float* __restrict__ O, const float* __restrict__ Wenc,
                 const float* __restrict__ benc, float* __restrict__ out)
{
    extern __shared__ float sm[];
    float* sWT  = sm;                       // 8448  (dead after encoder)
    float* sO   = sm + 8448;                // 16384 (dead after encoder)
    float* sHT  = sm + 24832;               // 16384: [r][b] quad-interleaved
    float* sB   = sm + 41216;               // 64
    float* sRed = sm + 41280;               // 2048
    float* sMs  = sm;                       // alias: M tile 512x32 = 16384
    // total 43328 floats = 173312 bytes

    const int t  = threadIdx.x;
    const int bb = blockIdx.x * BPC;

    // stage W_enc transposed: sWT[j][k] = Wenc[k*64+j]
#pragma unroll
    for (int c = 0; c < 16; c++) {
        int idx = t + TPB * c;              // 0..8191
        int k = idx >> 6, j = idx & 63;
        sWT[j * WT_STRIDE + k] = Wenc[idx];
    }
    if (t < 64) sB[t] = benc[t];

    const int rg = t >> 4;      // 32 row groups of 4 rows
    const int cg = t & 15;      // cols cg, cg+16, cg+32, cg+48
    const int r0 = rg * 4;

#pragma unroll 1
    for (int p = 0; p < 2; p++) {
        __syncthreads();

        const float4* osrc = (const float4*)(O + (size_t)(bb + 2 * p) * (64 * 128));
        float4* odst = (float4*)sO;
#pragma unroll
        for (int c = 0; c < 8; c++) odst[t + TPB * c] = osrc[t + TPB * c];
        __syncthreads();

        u64 acc2[4][4];
#pragma unroll
        for (int i = 0; i < 4; i++)
#pragma unroll
            for (int j = 0; j < 4; j++) acc2[i][j] = 0;

#pragma unroll 2
        for (int kk = 0; kk < 128; kk += 4) {
            ulonglong2 w0 = *(const ulonglong2*)&sWT[(cg +  0) * WT_STRIDE + kk];
            ulonglong2 w1 = *(const ulonglong2*)&sWT[(cg + 16) * WT_STRIDE + kk];
            ulonglong2 w2 = *(const ulonglong2*)&sWT[(cg + 32) * WT_STRIDE + kk];
            ulonglong2 w3 = *(const ulonglong2*)&sWT[(cg + 48) * WT_STRIDE + kk];
#pragma unroll
            for (int i = 0; i < 4; i++) {
                ulonglong2 o2 = *(const ulonglong2*)&sO[(r0 + i) * 128 + kk];
                ffma2(acc2[i][0], o2.x, w0.x); ffma2(acc2[i][0], o2.y, w0.y);
                ffma2(acc2[i][1], o2.x, w1.x); ffma2(acc2[i][1], o2.y, w1.y);
                ffma2(acc2[i][2], o2.x, w2.x); ffma2(acc2[i][2], o2.y, w2.y);
                ffma2(acc2[i][3], o2.x, w3.x); ffma2(acc2[i][3], o2.y, w3.y);
            }
        }

        float b0 = sB[cg], b1 = sB[cg + 16], b2 = sB[cg + 32], b3 = sB[cg + 48];
#pragma unroll
        for (int i = 0; i < 4; i++) {
            int row = r0 + i;
            int bl  = p * 2 + (row >> 6);
            int aa  = row & 63;
            int base = (aa * 64 + cg) * 4 + bl;   // sHT[r][b], r = aa*64+col
            sHT[base +   0] = fast_sigmoid(unpack_sum(acc2[i][0]) + b0);
            sHT[base +  64] = fast_sigmoid(unpack_sum(acc2[i][1]) + b1);
            sHT[base + 128] = fast_sigmoid(unpack_sum(acc2[i][2]) + b2);
            sHT[base + 192] = fast_sigmoid(unpack_sum(acc2[i][3]) + b3);
        }
    }

    // ---- decoder: out[b] = H0[b] @ M + const, M staged in 8 smem tiles ----
    const int w = t >> 5;       // 16 warps
    const int n = t & 31;
    u64 dacc[2] = {0, 0};       // (b0,b1), (b2,b3)

#pragma unroll 1
    for (int tile = 0; tile < 8; tile++) {
        __syncthreads();  // sHT ready (tile 0) / prev tile compute done
        const float4* msrc = (const float4*)(gM + tile * (512 * 32));
        float4* mdst = (float4*)sMs;
#pragma unroll
        for (int c = 0; c < 8; c++) mdst[t + TPB * c] = msrc[t + TPB * c];
        __syncthreads();

        const float* mrow = sMs + (w * 32) * 32 + n;
        const ulonglong2* hrow = (const ulonglong2*)&sHT[(tile * 512 + w * 32) * 4];
#pragma unroll 4
        for (int rr = 0; rr < 32; rr++) {
            u64 mm = dup2(mrow[rr * 32]);
            ulonglong2 h2 = hrow[rr];
            ffma2(dacc[0], h2.x, mm);
            ffma2(dacc[1], h2.y, mm);
        }
    }

    float v0, v1, v2, v3;
    unpack2(dacc[0], v0, v1);
    unpack2(dacc[1], v2, v3);
    sRed[(w * 4 + 0) * 32 + n] = v0;
    sRed[(w * 4 + 1) * 32 + n] = v1;
    sRed[(w * 4 + 2) * 32 + n] = v2;
    sRed[(w * 4 + 3) * 32 + n] = v3;
    __syncthreads();

    if (t < 128) {
        int b  = t >> 5;
        int nn = t & 31;
        float s = gConst[nn];
#pragma unroll
        for (int ww = 0; ww < 16; ww++) s += sRed[(ww * 4 + b) * 32 + nn];
        out[(size_t)(bb + b) * 32 + nn] = s;
    }
}

// ---------------------------------------------------------------------------
extern "C" void kernel_launch(void* const* d_in, const int* in_sizes, int n_in,
                              void* d_out, int out_size)
{
    const float* O    = (const float*)d_in[0];
    const float* Wenc = (const float*)d_in[1];
    const float* benc = (const float*)d_in[2];
    const float* W1   = (const float*)d_in[3];
    const float* b1   = (const float*)d_in[4];
    const float* W2   = (const float*)d_in[5];
    const float* b2   = (const float*)d_in[6];
    const float* W3   = (const float*)d_in[7];
    const float* b3   = (const float*)d_in[8];
    const float* W4   = (const float*)d_in[9];
    const float* b4   = (const float*)d_in[10];
    const float* Wdec = (const float*)d_in[11];
    const float* bdec = (const float*)d_in[12];
    float* out = (float*)d_out;

    cudaFuncSetAttribute(p1_compose,  cudaFuncAttributeMaxDynamicSharedMemorySize, 16960 * 4);
    cudaFuncSetAttribute(main_kernel, cudaFuncAttributeMaxDynamicSharedMemorySize, 43328 * 4);

    p0_wsum<<<8, 256>>>(Wdec);
    p1_compose<<<1, P1_TPB, 16960 * 4>>>(W1, b1, W2, b2, W3, b3, W4, b4, bdec);
    p2_buildM<<<64, 256>>>(Wdec);
    main_kernel<<<NBATCH / BPC, TPB, 43328 * 4>>>(O, Wenc, benc, out);
}

// round 17
// speedup vs baseline: 1.5436x; 1.5436x over previous
#include <cuda_runtime.h>
#include <cstddef>

// ============================================================================
// CommNetActor — algebraically collapsed + f32x2 FMA + MUFU-free sigmoid.
//
//   H0 = sigmoid(O @ W_enc + b_enc);  out[b] = H0[b].flatten() @ M + const
//
// R16 post-mortem: LDS.128 = 4 crossbar cyc always (512B lane data) ->
// 4x4 tile was crossbar-bound 2:1 (L1=81%, fma=36%). R17:
//  - encoder 8x8 register tile at 256 threads: crossbar 4(R+C)=64 == fma RC=64
//    per warp-kk -> both pipes saturate; scalar-FMA floor ~126us.
//  - BPC=8 (grid 1024): halves decoder gM L2 traffic per batch.
//  - decoder: 16 x 32KB M tiles, double-buffered (hide LDG latency).
//  - W/O staged in two K=64 chunks so everything fits in 222KB smem.
//  - H epilogue: slot-XOR (a>>3) + batch rotation (c&3) -> 2-way STS max;
//    decoder un-rotates with compile-time indices (unroll 4).
// ============================================================================

#define TPB 256
#define BPC 8
#define NBATCH 8192

typedef unsigned long long u64;

__device__ float gE[64 * 64];
__device__ float gT[64 * 32];
__device__ float gConst[32];
__device__ float gWsum[64 * 32];
__device__ float gM[4096 * 32];      // row-major: [a*64+k][n]

// ---------------------------------------------------------------------------
__device__ __forceinline__ void ffma2(u64& d, u64 a, u64 b) {
    asm("fma.rn.f32x2 %0, %1, %2, %0;" : "+l"(d) : "l"(a), "l"(b));
}
__device__ __forceinline__ u64 add2(u64 a, u64 b) {
    u64 d; asm("add.rn.f32x2 %0, %1, %2;" : "=l"(d) : "l"(a), "l"(b)); return d;
}
__device__ __forceinline__ float unpack_sum(u64 v) {
    float lo, hi;
    asm("mov.b64 {%0, %1}, %2;" : "=f"(lo), "=f"(hi) : "l"(v));
    return lo + hi;
}
__device__ __forceinline__ void unpack2(u64 v, float& lo, float& hi) {
    asm("mov.b64 {%0, %1}, %2;" : "=f"(lo), "=f"(hi) : "l"(v));
}
__device__ __forceinline__ u64 dup2(float m) {
    u64 d; asm("mov.b64 %0, {%1, %1};" : "=l"(d) : "f"(m)); return d;
}

// MUFU-free sigmoid: 1/(1+2^(-x*log2e)). ~18 FMA/ALU ops, rel err ~3e-6.
__device__ __forceinline__ float fast_sigmoid(float x) {
    float t = x * -1.44269504088896f;
    t = fminf(fmaxf(t, -126.0f), 126.0f);
    float fi = t + 12582912.0f;
    int   ib = __float_as_int(fi) - 0x4B400000;
    float f  = t - (fi - 12582912.0f);
    float p  = 1.3333558e-3f;
    p = fmaf(p, f, 9.6181291e-3f);
    p = fmaf(p, f, 5.5504109e-2f);
    p = fmaf(p, f, 2.4022651e-1f);
    p = fmaf(p, f, 6.9314718e-1f);
    p = fmaf(p, f, 1.0f);
    float e = __int_as_float(__float_as_int(p) + (int)((unsigned)ib << 23));
    float d = 1.0f + e;
    float r = __int_as_float(0x7EF311C3 - __float_as_int(d));
    r = r * (2.0f - d * r);
    r = r * (2.0f - d * r);
    return r;
}

// ---------------------------------------------------------------------------
// P0: Wsum[d][n] = sum_a Wdec[(a*64+d)][n].
// ---------------------------------------------------------------------------
__global__ void p0_wsum(const float* __restrict__ Wdec)
{
    int idx = blockIdx.x * 256 + threadIdx.x;
    float s = 0.0f;
#pragma unroll 8
    for (int a = 0; a < 64; a++) s += Wdec[a * 2048 + idx];
    gWsum[idx] = s;
}

// ---------------------------------------------------------------------------
// P1: compose 4 comm layers -> E, F, g; then T = (1/64) F Wsum, const.
// ---------------------------------------------------------------------------
#define P1_TPB 512
#define P1_WSTRIDE 68

__global__ void p1_compose(const float* __restrict__ W1, const float* __restrict__ b1,
                           const float* __restrict__ W2, const float* __restrict__ b2,
                           const float* __restrict__ W3, const float* __restrict__ b3,
                           const float* __restrict__ W4, const float* __restrict__ b4,
                           const float* __restrict__ bdec)
{
    extern __shared__ float sm[];
    float* sE   = sm;                      // 4096
    float* sF   = sm + 4096;               // 4096
    float* sWeT = sm + 8192;               // 4352
    float* sWbT = sm + 12544;              // 4352
    float* sG   = sm + 16896;              // 64

    const int t = threadIdx.x;

#pragma unroll
    for (int c = 0; c < 8; c++) {
        int idx = t + P1_TPB * c;
        sE[idx] = ((idx >> 6) == (idx & 63)) ? 1.0f : 0.0f;
        sF[idx] = 0.0f;
    }
    if (t < 64) sG[t] = 0.0f;

    const float* Ws[4] = {W1, W2, W3, W4};
    const float* bs[4] = {b1, b2, b3, b4};

    const int ti = t >> 5;
    const int tj = t & 31;
    const int i0 = ti * 4;

#pragma unroll 1
    for (int l = 0; l < 4; l++) {
        const float* W = Ws[l];
#pragma unroll
        for (int c = 0; c < 8; c++) {
            int idx = t + P1_TPB * c;
            int k = idx >> 6, j = idx & 63;
            float wt = W[idx];
            float wb = W[4096 + idx];
            sWeT[j * P1_WSTRIDE + k] = wt - wb * (1.0f / 64.0f);
            sWbT[j * P1_WSTRIDE + k] = wb;
        }
        __syncthreads();

        u64 aE[4][2], aF[4][2];
#pragma unroll
        for (int r = 0; r < 4; r++) {
            aE[r][0] = 0; aE[r][1] = 0; aF[r][0] = 0; aF[r][1] = 0;
        }

#pragma unroll 4
        for (int kk = 0; kk < 64; kk += 4) {
            ulonglong2 we0 = *(const ulonglong2*)&sWeT[tj * P1_WSTRIDE + kk];
            ulonglong2 we1 = *(const ulonglong2*)&sWeT[(tj + 32) * P1_WSTRIDE + kk];
            ulonglong2 wb0 = *(const ulonglong2*)&sWbT[tj * P1_WSTRIDE + kk];
            ulonglong2 wb1 = *(const ulonglong2*)&sWbT[(tj + 32) * P1_WSTRIDE + kk];
            u64 ws0x = add2(we0.x, wb0.x), ws0y = add2(we0.y, wb0.y);
            u64 ws1x = add2(we1.x, wb1.x), ws1y = add2(we1.y, wb1.y);
#pragma unroll
            for (int r = 0; r < 4; r++) {
                ulonglong2 e2 = *(const ulonglong2*)&sE[(i0 + r) * 64 + kk];
                ulonglong2 f2 = *(const ulonglong2*)&sF[(i0 + r) * 64 + kk];
                ffma2(aE[r][0], e2.x, we0.x); ffma2(aE[r][0], e2.y, we0.y);
                ffma2(aE[r][1], e2.x, we1.x); ffma2(aE[r][1], e2.y, we1.y);
                ffma2(aF[r][0], f2.x, ws0x); ffma2(aF[r][0], f2.y, ws0y);
                ffma2(aF[r][0], e2.x, wb0.x); ffma2(aF[r][0], e2.y, wb0.y);
                ffma2(aF[r][1], f2.x, ws1x); ffma2(aF[r][1], f2.y, ws1y);
                ffma2(aF[r][1], e2.x, wb1.x); ffma2(aF[r][1], e2.y, wb1.y);
            }
        }

        float gnew = 0.0f;
        if (t < 64) {
            for (int k = 0; k < 64; k++)
                gnew += sG[k] * (sWeT[t * P1_WSTRIDE + k] + sWbT[t * P1_WSTRIDE + k]);
            gnew += bs[l][t];
        }
        __syncthreads();

#pragma unroll
        for (int r = 0; r < 4; r++) {
            sE[(i0 + r) * 64 + tj]      = unpack_sum(aE[r][0]);
            sE[(i0 + r) * 64 + tj + 32] = unpack_sum(aE[r][1]);
            sF[(i0 + r) * 64 + tj]      = unpack_sum(aF[r][0]);
            sF[(i0 + r) * 64 + tj + 32] = unpack_sum(aF[r][1]);
        }
        if (t < 64) sG[t] = gnew;
    }
    __syncthreads();

    float* sWsum = sWeT;
#pragma unroll
    for (int c = 0; c < 4; c++) {
        int idx = t + P1_TPB * c;
        sWsum[idx] = gWsum[idx];
    }
    __syncthreads();

#pragma unroll
    for (int c = 0; c < 4; c++) {
        int idx = t + P1_TPB * c;
        int k = idx >> 5, n = idx & 31;
        float s = 0.0f;
#pragma unroll 8
        for (int d = 0; d < 64; d++) s += sF[k * 64 + d] * sWsum[d * 32 + n];
        gT[idx] = s * (1.0f / 64.0f);
    }
    if (t < 32) {
        float s = 0.0f;
        for (int d = 0; d < 64; d++) s += sG[d] * sWsum[d * 32 + t];
        gConst[t] = s + bdec[t];
    }
#pragma unroll
    for (int c = 0; c < 8; c++) { int idx = t + P1_TPB * c; gE[idx] = sE[idx]; }
}

// ---------------------------------------------------------------------------
// P2: gM[a*64+k][n] = sum_d E[k][d] * Wdec[(a*64+d)][n] + T[k][n]  (row-major)
// ---------------------------------------------------------------------------
__global__ void p2_buildM(const float* __restrict__ Wdec)
{
    __shared__ float sWd[2048];
    __shared__ float sE2[64 * 65];
    const int a = blockIdx.x;
    const int t = threadIdx.x;

#pragma unroll
    for (int c = 0; c < 8; c++)  sWd[t + 256 * c] = Wdec[a * 2048 + t + 256 * c];
#pragma unroll
    for (int c = 0; c < 16; c++) {
        int i = t + 256 * c;
        sE2[(i >> 6) * 65 + (i & 63)] = gE[i];
    }
    __syncthreads();

#pragma unroll
    for (int c = 0; c < 8; c++) {
        int idx = t + 256 * c;
        int k = idx >> 5, n = idx & 31;
        float acc = gT[idx];
#pragma unroll 8
        for (int d = 0; d < 64; d++)
            acc += sE2[k * 65 + d] * sWd[d * 32 + n];
        gM[a * 2048 + idx] = acc;
    }
}

// ---------------------------------------------------------------------------
// Main fused kernel. 256 threads, 8 batches/CTA.
// Encoder: 2 passes x 256 rows, 8x8 register tile, K staged in 2 chunks.
// sHT row (8 floats = 8 batches) stored with slot-XOR + batch rotation.
// Decoder: 16 x (256x32) M tiles, double-buffered in smem.
//
// smem layout (floats):
//   [0,4352)        sWT   (W^T chunk, [j][k2], stride 68)       } mainloop
//   [4352,20736)    sO    (256 rows x 64)                        } region X
//   [0,8192)        sMs0  } decoder tile buffers (alias region X)
//   [8192,16384)    sMs1  }
//   [20736,53504)   sHT   (4096 rows x 8 batches)
//   [53504,55552)   sRed  (8 warps x 8 b x 32 n)
//   [55552,55616)   sB
// total 55616 floats = 222464 B
// ---------------------------------------------------------------------------
__global__ __launch_bounds__(TPB, 1)
void main_kernel(const float* __restrict__ O, const float* __restrict__ Wenc,
                 const float* __restrict__ benc, float* __restrict__ out)
{
    extern __shared__ float sm[];
    float* sWT  = sm;
    float* sO   = sm + 4352;
    float* sMs0 = sm;
    float* sMs1 = sm + 8192;
    float* sHT  = sm + 20736;
    float* sRed = sm + 53504;
    float* sB   = sm + 55552;

    const int t   = threadIdx.x;
    const int bb8 = blockIdx.x * BPC;

    if (t < 64) sB[t] = benc[t];

    const int rg = t >> 3;      // 32 row groups of 8 rows
    const int cg = t & 7;       // cols cg, cg+8, ..., cg+56
    const int r0 = rg * 8;

    // ===================== encoder: 2 passes of 256 rows =====================
#pragma unroll 1
    for (int p = 0; p < 2; p++) {
        u64 acc[8][8];
#pragma unroll
        for (int i = 0; i < 8; i++)
#pragma unroll
            for (int j = 0; j < 8; j++) acc[i][j] = 0;

#pragma unroll 1
        for (int kc = 0; kc < 2; kc++) {
            __syncthreads();   // protect prev chunk reads / sB init
            // stage W chunk transposed: sWT[j][k2] = Wenc[(kc*64+k2)*64+j]
#pragma unroll
            for (int c = 0; c < 16; c++) {
                int idx = t + 256 * c;          // 0..4095
                int k2 = idx >> 6, j = idx & 63;
                sWT[j * 68 + k2] = Wenc[(kc * 64 + k2) * 64 + j];
            }
            // stage O chunk: 256 rows x 64 floats
            const float* obase = O + (size_t)(bb8 + 4 * p) * (64 * 128) + kc * 64;
#pragma unroll
            for (int c = 0; c < 16; c++) {
                int idx = t + 256 * c;          // 0..4095
                int row = idx >> 4, q = idx & 15;
                *(float4*)&sO[row * 64 + q * 4] =
                    *(const float4*)&obase[(size_t)row * 128 + q * 4];
            }
            __syncthreads();

#pragma unroll 1
            for (int kk = 0; kk < 64; kk += 4) {
                ulonglong2 wf[8];
#pragma unroll
                for (int j = 0; j < 8; j++)
                    wf[j] = *(const ulonglong2*)&sWT[(cg + 8 * j) * 68 + kk];
#pragma unroll
                for (int i = 0; i < 8; i++) {
                    ulonglong2 o2 = *(const ulonglong2*)&sO[(r0 + i) * 64 + kk];
#pragma unroll
                    for (int j = 0; j < 8; j++) {
                        ffma2(acc[i][j], o2.x, wf[j].x);
                        ffma2(acc[i][j], o2.y, wf[j].y);
                    }
                }
            }
        }

        // epilogue: bias + sigmoid -> sHT with slot-XOR + batch rotation
#pragma unroll
        for (int i = 0; i < 8; i++) {
            int rl   = r0 + i;                  // 0..255
            int bl   = p * 4 + (rl >> 6);       // batch 0..7
            int a    = rl & 63;
            int xorv = ((a >> 3) & 3) << 3;
#pragma unroll
            for (int j = 0; j < 8; j++) {
                int c    = cg + 8 * j;
                int word = (bl + 2 * (c & 3)) & 7;
                float h  = fast_sigmoid(unpack_sum(acc[i][j]) + sB[c]);
                sHT[(((a * 64 + c) * 8) ^ xorv) + word] = h;
            }
        }
    }
    __syncthreads();   // region X free; sHT complete

    // ======================= decoder: out = H @ M + c =======================
    const int w = t >> 5;       // 8 warps
    const int n = t & 31;
    u64 dacc[4] = {0, 0, 0, 0};   // batch pairs (0,1),(2,3),(4,5),(6,7)

    // stage tile 0
    {
        const float4* src = (const float4*)gM;
        float4* dst = (float4*)sMs0;
#pragma unroll
        for (int c = 0; c < 8; c++) dst[t + 256 * c] = src[t + 256 * c];
    }
    __syncthreads();

#pragma unroll 1
    for (int tt = 0; tt < 16; tt++) {
        const float* cur = (tt & 1) ? sMs1 : sMs0;
        if (tt < 15) {
            const float4* src = (const float4*)(gM + (tt + 1) * 8192);
            float4* dst = (float4*)((tt & 1) ? sMs0 : sMs1);
#pragma unroll
            for (int c = 0; c < 8; c++) dst[t + 256 * c] = src[t + 256 * c];
        }
        const float* mcol = cur + (w * 32) * 32 + n;
        const int rbase   = tt * 256 + w * 32;            // rbase & 3 == 0
        const int xorv    = ((tt >> 1) & 3) << 3;         // = ((r>>9)&3)<<3
#pragma unroll 4
        for (int rr = 0; rr < 32; rr++) {
            u64 mm = dup2(mcol[rr * 32]);
            const ulonglong2* rowp =
                (const ulonglong2*)&sHT[(((rbase + rr) * 8) ^ xorv)];
            ulonglong2 A = rowp[0];
            ulonglong2 B = rowp[1];
            u64 s[4] = {A.x, A.y, B.x, B.y};
            const int rm = rr & 3;   // static under unroll 4
            ffma2(dacc[0], s[(0 + rm) & 3], mm);
            ffma2(dacc[1], s[(1 + rm) & 3], mm);
            ffma2(dacc[2], s[(2 + rm) & 3], mm);
            ffma2(dacc[3], s[(3 + rm) & 3], mm);
        }
        __syncthreads();
    }

    // cross-warp reduction
#pragma unroll
    for (int pq = 0; pq < 4; pq++) {
        float v0, v1;
        unpack2(dacc[pq], v0, v1);
        sRed[w * 256 + (2 * pq + 0) * 32 + n] = v0;
        sRed[w * 256 + (2 * pq + 1) * 32 + n] = v1;
    }
    __syncthreads();

    {
        int b  = t >> 5;           // 0..7
        int nn = t & 31;
        float s = gConst[nn];
#pragma unroll
        for (int ww = 0; ww < 8; ww++) s += sRed[ww * 256 + b * 32 + nn];
        out[(size_t)(bb8 + b) * 32 + nn] = s;
    }
}

// ---------------------------------------------------------------------------
extern "C" void kernel_launch(void* const* d_in, const int* in_sizes, int n_in,
                              void* d_out, int out_size)
{
    const float* O    = (const float*)d_in[0];
    const float* Wenc = (const float*)d_in[1];
    const float* benc = (const float*)d_in[2];
    const float* W1   = (const float*)d_in[3];
    const float* b1   = (const float*)d_in[4];
    const float* W2   = (const float*)d_in[5];
    const float* b2   = (const float*)d_in[6];
    const float* W3   = (const float*)d_in[7];
    const float* b3   = (const float*)d_in[8];
    const float* W4   = (const float*)d_in[9];
    const float* b4   = (const float*)d_in[10];
    const float* Wdec = (const float*)d_in[11];
    const float* bdec = (const float*)d_in[12];
    float* out = (float*)d_out;

    cudaFuncSetAttribute(p1_compose,  cudaFuncAttributeMaxDynamicSharedMemorySize, 16960 * 4);
    cudaFuncSetAttribute(main_kernel, cudaFuncAttributeMaxDynamicSharedMemorySize, 55616 * 4);

    p0_wsum<<<8, 256>>>(Wdec);
    p1_compose<<<1, P1_TPB, 16960 * 4>>>(W1, b1, W2, b2, W3, b3, W4, b4, bdec);
    p2_buildM<<<64, 256>>>(Wdec);
    main_kernel<<<NBATCH / BPC, TPB, 55616 * 4>>>(O, Wenc, benc, out);
}